// round 6
// baseline (speedup 1.0000x reference)
#include <cuda_runtime.h>

#define NB     16     // batch
#define NT     256    // timesteps
#define NIN    6
#define NHID   256
#define NFEAT  64
#define NSTATE 64
#define NMOTOR 16
#define NUNF   6
#define EPSV   1e-8f

// scratch: state-independent sensory sums  [B,T,STATE]
__device__ float g_num[NB * NT * NSTATE];
__device__ float g_den[NB * NT * NSTATE];

__device__ __forceinline__ float tanh_fast(float x) {
    float y;
    asm("tanh.approx.f32 %0, %1;" : "=f"(y) : "f"(x));
    return y;
}

// two tanh for one MUFU slot: f32 args -> f16x2 tanh -> f32 results.
// args/accumulation stay f32; only the tanh in/out are f16.
__device__ __forceinline__ void tanh2_fast(float a0, float a1, float& t0, float& t1) {
    unsigned p, r;
    unsigned short lo, hi;
    asm("cvt.rn.f16x2.f32 %0, %1, %2;" : "=r"(p) : "f"(a1), "f"(a0)); // hi=a1, lo=a0
    asm("tanh.approx.f16x2 %0, %1;" : "=r"(r) : "r"(p));
    asm("mov.b32 {%0, %1}, %2;" : "=h"(lo), "=h"(hi) : "r"(r));
    asm("cvt.f32.f16 %0, %1;" : "=f"(t0) : "h"(lo));
    asm("cvt.f32.f16 %0, %1;" : "=f"(t1) : "h"(hi));
}

// ---------------------------------------------------------------------------
// Kernel 1: prenet (6->256 tanh ->64) + input affine + sensory synapse sums.
// One block per (b,t). Fully parallel: 4096 blocks x 256 threads.
// Kept in full f32 tanh.approx to reserve the error budget for the scan.
// ---------------------------------------------------------------------------
__global__ __launch_bounds__(256)
void prenet_sensory(const float* __restrict__ x,
                    const float* __restrict__ pw1, const float* __restrict__ pb1,
                    const float* __restrict__ pw2, const float* __restrict__ pb2,
                    const float* __restrict__ input_w, const float* __restrict__ input_b,
                    const float* __restrict__ sw,  const float* __restrict__ smu,
                    const float* __restrict__ ssig, const float* __restrict__ serev)
{
    __shared__ float hidden[NHID];
    __shared__ float featsh[NFEAT];
    __shared__ float pn[4][NSTATE];
    __shared__ float pd[4][NSTATE];

    const int bt  = blockIdx.x;
    const int tid = threadIdx.x;
    const int j   = tid & 63;
    const int q   = tid >> 6;      // 0..3

    // phase A: hidden[h] = tanh(x . pw1[:,h] + pb1[h]), h = tid
    {
        float xl[NIN];
        #pragma unroll
        for (int k = 0; k < NIN; k++) xl[k] = x[bt * NIN + k];
        float s = pb1[tid];
        #pragma unroll
        for (int k = 0; k < NIN; k++) s = fmaf(xl[k], pw1[k * NHID + tid], s);
        hidden[tid] = tanh_fast(s);
    }
    __syncthreads();

    // phase B: feat[j] = hidden . pw2[:,j] + pb2[j]; 4-way split over h
    {
        float acc = 0.0f;
        const int h0 = q * 64;
        #pragma unroll
        for (int h = 0; h < 64; h++)
            acc = fmaf(hidden[h0 + h], pw2[(h0 + h) * NFEAT + j], acc);
        pn[q][j] = acc;
    }
    __syncthreads();
    if (tid < NFEAT) {
        float f = pn[0][tid] + pn[1][tid] + pn[2][tid] + pn[3][tid] + pb2[tid];
        f = fmaf(f, input_w[tid], input_b[tid]);
        featsh[tid] = f;
    }
    __syncthreads();

    // phase C: sensory sums over FEAT; 4 groups of 16 feats each.
    // sigmoid(z) = 0.5*tanh(0.5 z)+0.5 ; a = sw*sigmoid = fma(0.5*sw, th, 0.5*sw)
    {
        float np = 0.0f, dp = 0.0f;
        const int f0 = q * 16;
        #pragma unroll
        for (int fi = 0; fi < 16; fi++) {
            const int f   = f0 + fi;
            const int idx = f * NSTATE + j;
            float hswv = 0.5f * sw[idx];
            float th = tanh_fast(0.5f * (featsh[f] - smu[idx]) * ssig[idx]);
            float a  = fmaf(hswv, th, hswv);
            np = fmaf(a, serev[idx], np);
            dp += a;
        }
        pn[q][j] = np;
        pd[q][j] = dp;
    }
    __syncthreads();
    if (tid < NSTATE) {
        g_num[bt * NSTATE + tid] = pn[0][tid] + pn[1][tid] + pn[2][tid] + pn[3][tid];
        g_den[bt * NSTATE + tid] = pd[0][tid] + pd[1][tid] + pd[2][tid] + pd[3][tid];
    }
}

// ---------------------------------------------------------------------------
// Kernel 2: sequential LTC scan. One CTA per batch (16 CTAs), 128 threads
// (= 4 warps, one per SMSP). j = tid>>1, g = tid&1 (32 rows per thread).
// f16x2 tanh halves the MUFU term; args + accumulation stay f32.
// One shfl level, double-buffered v, one barrier per unfold, LDG prefetch.
// ---------------------------------------------------------------------------
__global__ __launch_bounds__(128, 1)
void ltc_scan(const float* __restrict__ w_,    const float* __restrict__ mu_,
              const float* __restrict__ sigma_, const float* __restrict__ erev_,
              const float* __restrict__ gleak,  const float* __restrict__ vleak,
              const float* __restrict__ cm,
              const float* __restrict__ ow,     const float* __restrict__ ob,
              float* __restrict__ out)
{
    __shared__ __align__(16) float vsh[2][NSTATE];

    const int b   = blockIdx.x;
    const int tid = threadIdx.x;
    const int j   = tid >> 1;      // 0..63 post neuron
    const int g   = tid & 1;       // 0..1 row group (32 rows each)

    // per-thread synapse constants for rows i = g*32..g*32+31, column j.
    //   arg_k = v_i * (0.5*sigma) - 0.5*mu*sigma
    //   np    = swe + sum hwe*tanh ,  dp = swv + sum hwv*tanh
    float hs[32], hb[32], hwe[32], hwv[32];
    float swe = 0.0f, swv = 0.0f;
    #pragma unroll
    for (int k = 0; k < 32; k++) {
        const int i   = g * 32 + k;
        const int idx = i * NSTATE + j;
        float wv  = w_[idx];
        float er  = erev_[idx];
        float sgv = sigma_[idx];
        float muv = mu_[idx];
        hwv[k] = 0.5f * wv;
        hwe[k] = 0.5f * wv * er;
        hs[k]  = 0.5f * sgv;
        hb[k]  = 0.5f * muv * sgv;
        swe += hwe[k];
        swv += hwv[k];
    }

    // per-j scalars (replicated across the 2 lanes sharing j)
    const float cm_t = cm[j] * (float)NUNF;
    const float gl   = gleak[j];
    const float leak = gl * vleak[j];
    const float denc = cm_t + gl + EPSV;   // constant part of denominator
    float owv = 0.0f, obv = 0.0f;
    if (j < NMOTOR) { owv = ow[j]; obv = ob[j]; }

    if (tid < NSTATE) vsh[0][tid] = 0.0f;
    float vj = 0.0f;
    __syncthreads();

    const float* nb   = g_num + b * NT * NSTATE;
    const float* db   = g_den + b * NT * NSTATE;
    float*       outb = out   + b * NT * NMOTOR;

    float ns = nb[j];
    float ds = db[j];

    for (int t = 0; t < NT; t++) {
        // issue next-t loads immediately; consumed only after 6 unfolds
        const int tn = (t + 1 < NT) ? (t + 1) : t;
        float ns_next = nb[tn * NSTATE + j];
        float ds_next = db[tn * NSTATE + j];

        const float nsl = ns + leak;   // numerator constant for this t
        const float dsl = ds + denc;   // denominator constant for this t

        #pragma unroll
        for (int u = 0; u < NUNF; u++) {
            const int cur = u & 1;

            // 4 partial accumulators each; consume v in float4 chunks
            float np0 = swe, np1 = 0.f, np2 = 0.f, np3 = 0.f;
            float dp0 = swv, dp1 = 0.f, dp2 = 0.f, dp3 = 0.f;
            #pragma unroll
            for (int c = 0; c < 8; c++) {
                float4 vq = *reinterpret_cast<const float4*>(&vsh[cur][g * 32 + c * 4]);
                const int k = c * 4;
                float a0 = fmaf(vq.x, hs[k + 0], -hb[k + 0]);
                float a1 = fmaf(vq.y, hs[k + 1], -hb[k + 1]);
                float a2 = fmaf(vq.z, hs[k + 2], -hb[k + 2]);
                float a3 = fmaf(vq.w, hs[k + 3], -hb[k + 3]);
                float t0, t1, t2, t3;
                tanh2_fast(a0, a1, t0, t1);
                tanh2_fast(a2, a3, t2, t3);
                np0 = fmaf(hwe[k + 0], t0, np0);
                np1 = fmaf(hwe[k + 1], t1, np1);
                np2 = fmaf(hwe[k + 2], t2, np2);
                np3 = fmaf(hwe[k + 3], t3, np3);
                dp0 = fmaf(hwv[k + 0], t0, dp0);
                dp1 = fmaf(hwv[k + 1], t1, dp1);
                dp2 = fmaf(hwv[k + 2], t2, dp2);
                dp3 = fmaf(hwv[k + 3], t3, dp3);
            }
            float dp = (dp0 + dp1) + (dp2 + dp3);
            float np = (np0 + np1) + (np2 + np3);

            // reduce across the 2 lanes sharing j (lane bit 0); dp first so the
            // reciprocal can start while np finishes
            dp += __shfl_xor_sync(0xffffffffu, dp, 1);
            np += __shfl_xor_sync(0xffffffffu, np, 1);

            float denom = dp + dsl;
            float numer = fmaf(cm_t, vj, np + nsl);
            vj = __fdividef(numer, denom);

            if (g == 0) vsh[cur ^ 1][j] = vj;   // write OTHER buffer: no hazard
            __syncthreads();
        }

        if (j < NMOTOR && g == 0)
            outb[t * NMOTOR + j] = fmaf(vj, owv, obv);

        ns = ns_next;
        ds = ds_next;
    }
}

// ---------------------------------------------------------------------------
extern "C" void kernel_launch(void* const* d_in, const int* in_sizes, int n_in,
                              void* d_out, int out_size)
{
    const float* x        = (const float*)d_in[0];
    const float* pw1      = (const float*)d_in[1];
    const float* pb1      = (const float*)d_in[2];
    const float* pw2      = (const float*)d_in[3];
    const float* pb2      = (const float*)d_in[4];
    const float* input_w  = (const float*)d_in[5];
    const float* input_b  = (const float*)d_in[6];
    const float* sw       = (const float*)d_in[7];
    const float* smu      = (const float*)d_in[8];
    const float* ssig     = (const float*)d_in[9];
    const float* serev    = (const float*)d_in[10];
    const float* w_       = (const float*)d_in[11];
    const float* mu_      = (const float*)d_in[12];
    const float* sigma_   = (const float*)d_in[13];
    const float* erev_    = (const float*)d_in[14];
    const float* gleak    = (const float*)d_in[15];
    const float* vleak    = (const float*)d_in[16];
    const float* cm       = (const float*)d_in[17];
    const float* ow       = (const float*)d_in[18];
    const float* ob       = (const float*)d_in[19];
    float* out = (float*)d_out;

    prenet_sensory<<<NB * NT, 256>>>(x, pw1, pb1, pw2, pb2, input_w, input_b,
                                     sw, smu, ssig, serev);
    ltc_scan<<<NB, 128>>>(w_, mu_, sigma_, erev_, gleak, vleak, cm, ow, ob, out);
}

// round 7
// speedup vs baseline: 1.1153x; 1.1153x over previous
#include <cuda_runtime.h>

#define NB     16     // batch
#define NT     256    // timesteps
#define NIN    6
#define NHID   256
#define NFEAT  64
#define NSTATE 64
#define NMOTOR 16
#define NUNF   6
#define TBCH   8      // timesteps per prenet block
#define EPSV   1e-8f

// scratch: state-independent sensory sums  [B,T,STATE]
__device__ float g_num[NB * NT * NSTATE];
__device__ float g_den[NB * NT * NSTATE];

__device__ __forceinline__ float tanh_fast(float x) {
    float y;
    asm("tanh.approx.f32 %0, %1;" : "=f"(y) : "f"(x));
    return y;
}

__device__ __forceinline__ float fastdiv(float a, float b) {
    float r, q;
    asm("rcp.approx.f32 %0, %1;" : "=f"(r) : "f"(b));
    asm("mul.f32 %0, %1, %2;" : "=f"(q) : "f"(a), "f"(r));
    return q;
}

// ---------------------------------------------------------------------------
// Kernel 1: prenet (6->256 tanh ->64) + input affine + sensory synapse sums.
// TBCH timesteps per block (512 blocks x 256 threads): pw1 row + the thread's
// 64 pw2 weights live in registers across the chunk, killing the per-timestep
// weight re-fetch that dominated the 4096-block version.
// ---------------------------------------------------------------------------
__global__ __launch_bounds__(256, 1)
void prenet_sensory(const float* __restrict__ x,
                    const float* __restrict__ pw1, const float* __restrict__ pb1,
                    const float* __restrict__ pw2, const float* __restrict__ pb2,
                    const float* __restrict__ input_w, const float* __restrict__ input_b,
                    const float* __restrict__ sw,  const float* __restrict__ smu,
                    const float* __restrict__ ssig, const float* __restrict__ serev)
{
    __shared__ float hidden[NHID];
    __shared__ float featsh[NFEAT];
    __shared__ float pn[4][NSTATE];
    __shared__ float pd[4][NSTATE];

    const int bt0 = blockIdx.x * TBCH;
    const int tid = threadIdx.x;
    const int j   = tid & 63;
    const int q   = tid >> 6;      // 0..3

    // register-cached weights, reused for all TBCH timesteps
    float w1[NIN];
    #pragma unroll
    for (int k = 0; k < NIN; k++) w1[k] = pw1[k * NHID + tid];
    const float b1 = pb1[tid];

    float w2[64];
    {
        const int h0 = q * 64;
        #pragma unroll
        for (int h = 0; h < 64; h++) w2[h] = pw2[(h0 + h) * NFEAT + j];
    }

    for (int tt = 0; tt < TBCH; tt++) {
        const int bt = bt0 + tt;

        // phase A: hidden[h] = tanh(x . pw1[:,h] + pb1[h]), h = tid
        {
            float s = b1;
            #pragma unroll
            for (int k = 0; k < NIN; k++) s = fmaf(x[bt * NIN + k], w1[k], s);
            hidden[tid] = tanh_fast(s);
        }
        __syncthreads();

        // phase B: feat[j] partial over 64 hidden; weights from registers
        {
            float acc = 0.0f;
            const int h0 = q * 64;
            #pragma unroll
            for (int h = 0; h < 64; h++)
                acc = fmaf(hidden[h0 + h], w2[h], acc);
            pn[q][j] = acc;
        }
        __syncthreads();
        if (tid < NFEAT) {
            float f = pn[0][tid] + pn[1][tid] + pn[2][tid] + pn[3][tid] + pb2[tid];
            f = fmaf(f, input_w[tid], input_b[tid]);
            featsh[tid] = f;
        }
        __syncthreads();

        // phase C: sensory sums over FEAT; 4 groups of 16 feats (tables L1-hot).
        // sigmoid(z) = 0.5*tanh(0.5 z)+0.5 ; a = fma(0.5*sw, th, 0.5*sw)
        {
            float np = 0.0f, dp = 0.0f;
            const int f0 = q * 16;
            #pragma unroll
            for (int fi = 0; fi < 16; fi++) {
                const int f   = f0 + fi;
                const int idx = f * NSTATE + j;
                float hswv = 0.5f * sw[idx];
                float th = tanh_fast(0.5f * (featsh[f] - smu[idx]) * ssig[idx]);
                float a  = fmaf(hswv, th, hswv);
                np = fmaf(a, serev[idx], np);
                dp += a;
            }
            pn[q][j] = np;
            pd[q][j] = dp;
        }
        __syncthreads();
        if (tid < NSTATE) {
            g_num[bt * NSTATE + tid] = pn[0][tid] + pn[1][tid] + pn[2][tid] + pn[3][tid];
            g_den[bt * NSTATE + tid] = pd[0][tid] + pd[1][tid] + pd[2][tid] + pd[3][tid];
        }
        __syncthreads();   // hidden/pn reused next iteration
    }
}

// ---------------------------------------------------------------------------
// Kernel 2: sequential LTC scan (R5 design: best measured @ 407us).
// One CTA per batch (16 CTAs), 128 threads (4 warps, one per SMSP).
// j = tid>>1, g = tid&1 (32 rows per thread). f32 tanh.approx only.
// One shfl level, double-buffered v, one barrier per unfold, LDG prefetch.
// ---------------------------------------------------------------------------
__global__ __launch_bounds__(128, 1)
void ltc_scan(const float* __restrict__ w_,    const float* __restrict__ mu_,
              const float* __restrict__ sigma_, const float* __restrict__ erev_,
              const float* __restrict__ gleak,  const float* __restrict__ vleak,
              const float* __restrict__ cm,
              const float* __restrict__ ow,     const float* __restrict__ ob,
              float* __restrict__ out)
{
    __shared__ __align__(16) float vsh[2][NSTATE];

    const int b   = blockIdx.x;
    const int tid = threadIdx.x;
    const int j   = tid >> 1;      // 0..63 post neuron
    const int g   = tid & 1;       // 0..1 row group (32 rows each)

    // per-thread synapse constants for rows i = g*32..g*32+31, column j.
    //   arg_k = v_i * (0.5*sigma) - 0.5*mu*sigma
    //   np    = swe + sum hwe*tanh ,  dp = swv + sum hwv*tanh
    float hs[32], hb[32], hwe[32], hwv[32];
    float swe = 0.0f, swv = 0.0f;
    #pragma unroll
    for (int k = 0; k < 32; k++) {
        const int i   = g * 32 + k;
        const int idx = i * NSTATE + j;
        float wv  = w_[idx];
        float er  = erev_[idx];
        float sgv = sigma_[idx];
        float muv = mu_[idx];
        hwv[k] = 0.5f * wv;
        hwe[k] = 0.5f * wv * er;
        hs[k]  = 0.5f * sgv;
        hb[k]  = 0.5f * muv * sgv;
        swe += hwe[k];
        swv += hwv[k];
    }

    // per-j scalars (replicated across the 2 lanes sharing j)
    const float cm_t = cm[j] * (float)NUNF;
    const float gl   = gleak[j];
    const float leak = gl * vleak[j];
    const float denc = cm_t + gl + EPSV;   // constant part of denominator
    float owv = 0.0f, obv = 0.0f;
    if (j < NMOTOR) { owv = ow[j]; obv = ob[j]; }

    if (tid < NSTATE) vsh[0][tid] = 0.0f;
    float vj = 0.0f;
    __syncthreads();

    const float* nb   = g_num + b * NT * NSTATE;
    const float* db   = g_den + b * NT * NSTATE;
    float*       outb = out   + b * NT * NMOTOR;

    float ns = nb[j];
    float ds = db[j];

    for (int t = 0; t < NT; t++) {
        // issue next-t loads immediately; consumed only after 6 unfolds
        const int tn = (t + 1 < NT) ? (t + 1) : t;
        float ns_next = nb[tn * NSTATE + j];
        float ds_next = db[tn * NSTATE + j];

        const float nsl = ns + leak;   // numerator constant for this t
        const float dsl = ds + denc;   // denominator constant for this t

        #pragma unroll
        for (int u = 0; u < NUNF; u++) {
            const int cur = u & 1;

            // 4 partial accumulators each; consume v in float4 chunks
            float np0 = swe, np1 = 0.f, np2 = 0.f, np3 = 0.f;
            float dp0 = swv, dp1 = 0.f, dp2 = 0.f, dp3 = 0.f;
            #pragma unroll
            for (int c = 0; c < 8; c++) {
                float4 vq = *reinterpret_cast<const float4*>(&vsh[cur][g * 32 + c * 4]);
                const int k = c * 4;
                float t0 = tanh_fast(fmaf(vq.x, hs[k + 0], -hb[k + 0]));
                float t1 = tanh_fast(fmaf(vq.y, hs[k + 1], -hb[k + 1]));
                float t2 = tanh_fast(fmaf(vq.z, hs[k + 2], -hb[k + 2]));
                float t3 = tanh_fast(fmaf(vq.w, hs[k + 3], -hb[k + 3]));
                np0 = fmaf(hwe[k + 0], t0, np0);
                np1 = fmaf(hwe[k + 1], t1, np1);
                np2 = fmaf(hwe[k + 2], t2, np2);
                np3 = fmaf(hwe[k + 3], t3, np3);
                dp0 = fmaf(hwv[k + 0], t0, dp0);
                dp1 = fmaf(hwv[k + 1], t1, dp1);
                dp2 = fmaf(hwv[k + 2], t2, dp2);
                dp3 = fmaf(hwv[k + 3], t3, dp3);
            }
            float dp = (dp0 + dp1) + (dp2 + dp3);
            float np = (np0 + np1) + (np2 + np3);

            // reduce across the 2 lanes sharing j (lane bit 0); dp first so the
            // reciprocal can start while np finishes
            dp += __shfl_xor_sync(0xffffffffu, dp, 1);
            np += __shfl_xor_sync(0xffffffffu, np, 1);

            float denom = dp + dsl;
            float numer = fmaf(cm_t, vj, np + nsl);
            vj = fastdiv(numer, denom);

            if (g == 0) vsh[cur ^ 1][j] = vj;   // write OTHER buffer: no hazard
            __syncthreads();
        }

        if (j < NMOTOR && g == 0)
            outb[t * NMOTOR + j] = fmaf(vj, owv, obv);

        ns = ns_next;
        ds = ds_next;
    }
}

// ---------------------------------------------------------------------------
extern "C" void kernel_launch(void* const* d_in, const int* in_sizes, int n_in,
                              void* d_out, int out_size)
{
    const float* x        = (const float*)d_in[0];
    const float* pw1      = (const float*)d_in[1];
    const float* pb1      = (const float*)d_in[2];
    const float* pw2      = (const float*)d_in[3];
    const float* pb2      = (const float*)d_in[4];
    const float* input_w  = (const float*)d_in[5];
    const float* input_b  = (const float*)d_in[6];
    const float* sw       = (const float*)d_in[7];
    const float* smu      = (const float*)d_in[8];
    const float* ssig     = (const float*)d_in[9];
    const float* serev    = (const float*)d_in[10];
    const float* w_       = (const float*)d_in[11];
    const float* mu_      = (const float*)d_in[12];
    const float* sigma_   = (const float*)d_in[13];
    const float* erev_    = (const float*)d_in[14];
    const float* gleak    = (const float*)d_in[15];
    const float* vleak    = (const float*)d_in[16];
    const float* cm       = (const float*)d_in[17];
    const float* ow       = (const float*)d_in[18];
    const float* ob       = (const float*)d_in[19];
    float* out = (float*)d_out;

    prenet_sensory<<<NB * NT / TBCH, 256>>>(x, pw1, pb1, pw2, pb2, input_w, input_b,
                                            sw, smu, ssig, serev);
    ltc_scan<<<NB, 128>>>(w_, mu_, sigma_, erev_, gleak, vleak, cm, ow, ob, out);
}